// round 13
// baseline (speedup 1.0000x reference)
#include <cuda_runtime.h>
#include <cstdint>
#include <math.h>

#define TOKENS 8192
#define HIDDEN 7168
#define NEXP   256
#define TOP_K  8

// ---- GEMM: CTA 128x128xK896, 8 warps (2x4, warp 64x32), 2 CTAs/SM ----------
// [R9 mainloop byte-identical: zero register margin — do not touch]
#define BM 128
#define BN 128
#define BK 32
#define KSPLIT 8
#define KSLICE (HIDDEN / KSPLIT)    // 896
#define KT_ITERS (KSLICE / BK)      // 28
#define STAGES 3
#define NTHREADS 256
#define MTILES (TOKENS / BM)        // 64
#define ARRIVALS (2 * KSPLIT)       // 16 units per mtile
#define ASTRIDE 36                  // banks (4m+k) all distinct
#define BSTRIDE 136                 // banks (8k+n) all distinct
#define A_FLOATS (BM * ASTRIDE)     // 4608
#define B_FLOATS (BK * BSTRIDE)     // 4352
#define STAGE_FLOATS (A_FLOATS + B_FLOATS)      // 8960
#define SMEM_DYN (STAGES * STAGE_FLOATS * 4)    // 107520 B -> 2 CTAs/SM

// device scratch (no cudaMalloc allowed)
__device__ float g_part[KSPLIT][(size_t)TOKENS * NEXP];
__device__ unsigned int g_done[MTILES];   // zero at load; route blocks self-clean

__device__ __forceinline__ uint32_t smem_u32(const void* p) {
    uint32_t a;
    asm("{ .reg .u64 t; cvta.to.shared.u64 t, %1; cvt.u32.u64 %0, t; }" : "=r"(a) : "l"(p));
    return a;
}
__device__ __forceinline__ void cp_async16(uint32_t s, const void* g) {
    asm volatile("cp.async.cg.shared.global [%0], [%1], 16;\n" :: "r"(s), "l"(g));
}
__device__ __forceinline__ void mma_tf32(float* c, const uint32_t* a, const uint32_t* b) {
    asm volatile(
        "mma.sync.aligned.m16n8k8.row.col.f32.tf32.tf32.f32 "
        "{%0,%1,%2,%3}, {%4,%5,%6,%7}, {%8,%9}, {%0,%1,%2,%3};\n"
        : "+f"(c[0]), "+f"(c[1]), "+f"(c[2]), "+f"(c[3])
        : "r"(a[0]), "r"(a[1]), "r"(a[2]), "r"(a[3]), "r"(b[0]), "r"(b[1]));
}
__device__ __forceinline__ unsigned ld_acquire(const unsigned* p) {
    unsigned v;
    asm volatile("ld.acquire.gpu.global.u32 %0, [%1];" : "=r"(v) : "l"(p));
    return v;
}

// ---------------------------------------------------------------------------
// GEMM: g_part[ksl] = A[mtile rows, kslice] * B[kslice, ntile cols]
// grid (16, 64): x = ntile + 2*ksl, y = mtile.  1024 CTAs, ~3.5 waves.
// PDL: triggers dependents after prologue; signals g_done[mtile] at end.
// ---------------------------------------------------------------------------
__global__ __launch_bounds__(NTHREADS, 2) void gemm_kernel(
    const float* __restrict__ A, const float* __restrict__ B)
{
    extern __shared__ float smem[];

    const int tid    = threadIdx.x;
    const int wid    = tid >> 5;
    const int lane   = tid & 31;
    const int warp_m = wid >> 2;    // 0..1 -> 64 rows
    const int warp_n = wid & 3;     // 0..3 -> 32 cols
    const int ntile  = blockIdx.x & 1;
    const int ksl    = blockIdx.x >> 1;
    const int brow   = blockIdx.y * BM;
    const int bcol   = ntile * BN;
    const int kbase  = ksl * KSLICE;

    // per-thread load slots: A 1024 chunks (4/thr), B 1024 chunks (4/thr)
    const float* agp[4]; uint32_t aof[4];
    const float* bgp[4]; uint32_t bof[4];
    #pragma unroll
    for (int j = 0; j < 4; j++) {
        int i = tid + j * 256;          // A: 128 rows x 8 chunks of 16B
        int r = i >> 3, c = i & 7;
        aof[j] = (uint32_t)(r * ASTRIDE + c * 4) * 4u;
        agp[j] = A + (size_t)(brow + r) * HIDDEN + kbase + c * 4;
    }
    #pragma unroll
    for (int j = 0; j < 4; j++) {
        int i = tid + j * 256;          // B: 32 rows x 32 chunks of 16B
        int r = i >> 5, c = i & 31;
        bof[j] = (uint32_t)(A_FLOATS + r * BSTRIDE + c * 4) * 4u;
        bgp[j] = B + (size_t)(kbase + r) * NEXP + bcol + c * 4;
    }
    const uint32_t smem_base = smem_u32(smem);

    auto load_stage = [&](int kt) {
        const uint32_t sbase = smem_base + (uint32_t)(kt % STAGES) * (STAGE_FLOATS * 4);
        const int koff = kt * BK;
        #pragma unroll
        for (int j = 0; j < 4; j++) cp_async16(sbase + aof[j], agp[j] + koff);
        #pragma unroll
        for (int j = 0; j < 4; j++) cp_async16(sbase + bof[j], bgp[j] + (size_t)koff * NEXP);
        asm volatile("cp.async.commit_group;\n" ::: "memory");
    };

    float acc[4][4][4];
    #pragma unroll
    for (int mt = 0; mt < 4; mt++)
        #pragma unroll
        for (int nt = 0; nt < 4; nt++)
            #pragma unroll
            for (int i = 0; i < 4; i++) acc[mt][nt][i] = 0.f;

    load_stage(0);
    load_stage(1);

    // PDL: allow the route kernel to launch once every GEMM CTA has started.
    asm volatile("griddepcontrol.launch_dependents;");

    const int arow0 = warp_m * 64 + (lane >> 2);
    const int bcol0 = warp_n * 32 + (lane >> 2);
    const int ak    = lane & 3;

    for (int kt = 0; kt < KT_ITERS; kt++) {
        if (kt == KT_ITERS - 1)
            asm volatile("cp.async.wait_group 0;\n" ::: "memory");
        else
            asm volatile("cp.async.wait_group 1;\n" ::: "memory");
        __syncthreads();      // single barrier per kt (also guards buffer reuse)

        if (kt + 2 < KT_ITERS) load_stage(kt + 2);

        const float* As = smem + (size_t)(kt % STAGES) * STAGE_FLOATS;
        const float* Bs = As + A_FLOATS;

        #pragma unroll
        for (int ks = 0; ks < 4; ks++) {
            const int kk = ks * 8;
            uint32_t afr[4][4];
            uint32_t bfr[4][2];
            #pragma unroll
            for (int mt = 0; mt < 4; mt++) {
                const int m0 = arow0 + mt * 16;
                const int cc = kk + ak;
                afr[mt][0] = __float_as_uint(As[m0 * ASTRIDE + cc]);
                afr[mt][1] = __float_as_uint(As[(m0 + 8) * ASTRIDE + cc]);
                afr[mt][2] = __float_as_uint(As[m0 * ASTRIDE + cc + 4]);
                afr[mt][3] = __float_as_uint(As[(m0 + 8) * ASTRIDE + cc + 4]);
            }
            #pragma unroll
            for (int nt = 0; nt < 4; nt++) {
                const int n0 = bcol0 + nt * 8;
                const int kr = kk + ak;
                bfr[nt][0] = __float_as_uint(Bs[kr * BSTRIDE + n0]);
                bfr[nt][1] = __float_as_uint(Bs[(kr + 4) * BSTRIDE + n0]);
            }
            #pragma unroll
            for (int mt = 0; mt < 4; mt++)
                #pragma unroll
                for (int nt = 0; nt < 4; nt++)
                    mma_tf32(acc[mt][nt], afr[mt], bfr[nt]);
        }
    }

    // epilogue: plain stores into this k-slice's partial buffer
    float* dst = g_part[ksl];
    #pragma unroll
    for (int mt = 0; mt < 4; mt++) {
        #pragma unroll
        for (int nt = 0; nt < 4; nt++) {
            int row = brow + warp_m * 64 + mt * 16 + (lane >> 2);
            int col = bcol + warp_n * 32 + nt * 8 + (lane & 3) * 2;
            *(float2*)&dst[(size_t)row * NEXP + col] =
                make_float2(acc[mt][nt][0], acc[mt][nt][1]);
            *(float2*)&dst[(size_t)(row + 8) * NEXP + col] =
                make_float2(acc[mt][nt][2], acc[mt][nt][3]);
        }
    }

    // completion signal for the overlapped route kernel
    __threadfence();
    __syncthreads();
    if (tid == 0) atomicAdd(&g_done[blockIdx.y], 1u);
}

// ---------------------------------------------------------------------------
// Route kernel (PDL secondary): 64 blocks, one per mtile. Each block waits on
// its mtile's 16 GEMM units, then routes 128 tokens (8 warps x 16).
// ---------------------------------------------------------------------------
__global__ __launch_bounds__(256) void route_kernel(
    const float* __restrict__ bias, float* __restrict__ out)
{
    const int mtile = blockIdx.x;
    const int wid   = threadIdx.x >> 5;
    const int lane  = threadIdx.x & 31;

    if (threadIdx.x == 0) {
        while (ld_acquire(&g_done[mtile]) < (unsigned)ARRIVALS) __nanosleep(128);
    }
    __syncthreads();    // broadcast readiness; acquire + barrier orders the reads

    float bias_r[8];
    #pragma unroll
    for (int i = 0; i < 8; i++) bias_r[i] = __ldg(&bias[lane * 8 + i]);

    for (int t16 = 0; t16 < 16; t16++) {
        const int token = mtile * BM + wid * 16 + t16;

        // sum the 8 k-slice partials in fixed order (deterministic)
        float l[8] = {0.f, 0.f, 0.f, 0.f, 0.f, 0.f, 0.f, 0.f};
        #pragma unroll
        for (int b = 0; b < KSPLIT; b++) {
            const float4* p = (const float4*)(g_part[b] + (size_t)token * NEXP + lane * 8);
            float4 x = p[0], y = p[1];
            l[0] += x.x; l[1] += x.y; l[2] += x.z; l[3] += x.w;
            l[4] += y.x; l[5] += y.y; l[6] += y.z; l[7] += y.w;
        }

        float s[8];
        #pragma unroll
        for (int i = 0; i < 8; i++) {
            float sc = 1.f / (1.f + __expf(-l[i]));
            s[i] = sc + bias_r[i];
        }

        // per-lane top-2, merged across the 4 lanes of the group
        float m1 = -INFINITY, m2 = -INFINITY;
        #pragma unroll
        for (int i = 0; i < 8; i++) {
            float v = s[i];
            if (v > m1) { m2 = m1; m1 = v; }
            else if (v > m2) { m2 = v; }
        }
        #pragma unroll
        for (int off = 1; off <= 2; off <<= 1) {
            float o1 = __shfl_xor_sync(0xffffffffu, m1, off);
            float o2 = __shfl_xor_sync(0xffffffffu, m2, off);
            float hi = fmaxf(m1, o1);
            float lo = fmaxf(fminf(m1, o1), fmaxf(m2, o2));
            m1 = hi; m2 = lo;
        }
        float gsum = m1 + m2;

        float gs[8];
        #pragma unroll
        for (int g = 0; g < 8; g++)
            gs[g] = __shfl_sync(0xffffffffu, gsum, g * 4);

        const int myg = lane >> 2;
        int rank = 0;
        #pragma unroll
        for (int h = 0; h < 8; h++)
            if (gs[h] > gs[myg] || (gs[h] == gs[myg] && h < myg)) rank++;
        const bool sel = rank < 4;

        float vals[8];
        #pragma unroll
        for (int i = 0; i < 8; i++) vals[i] = sel ? s[i] : 0.f;

        float w[TOP_K];
        #pragma unroll
        for (int t = 0; t < TOP_K; t++) {
            float bv = vals[0];
            int bi = 0;
            #pragma unroll
            for (int i = 1; i < 8; i++)
                if (vals[i] > bv) { bv = vals[i]; bi = i; }
            int bidx = lane * 8 + bi;
            #pragma unroll
            for (int off = 16; off >= 1; off >>= 1) {
                float ov = __shfl_xor_sync(0xffffffffu, bv, off);
                int   oi = __shfl_xor_sync(0xffffffffu, bidx, off);
                if (ov > bv || (ov == bv && oi < bidx)) { bv = ov; bidx = oi; }
            }
            w[t] = bv;
            if ((bidx >> 3) == lane) vals[bidx & 7] = -INFINITY;
        }

        float denom = 1e-20f;
        #pragma unroll
        for (int t = 0; t < TOP_K; t++) denom += w[t];
        const float scale = 2.5f / denom;

        if (lane == 0) {
            #pragma unroll
            for (int t = 0; t < TOP_K; t++)
                out[(size_t)token * TOP_K + t] = w[t] * scale;
        }
    }

    __syncthreads();
    if (threadIdx.x == 0) g_done[mtile] = 0u;   // self-clean for graph replays
}

// ---------------------------------------------------------------------------
extern "C" void kernel_launch(void* const* d_in, const int* in_sizes, int n_in,
                              void* d_out, int out_size)
{
    (void)in_sizes; (void)n_in; (void)out_size;
    const float* hs   = (const float*)d_in[0];  // [8192, 7168]
    const float* W    = (const float*)d_in[1];  // [7168, 256]
    const float* bias = (const float*)d_in[2];  // [256]
    float* out = (float*)d_out;                 // [8192, 8]

    cudaFuncSetAttribute(gemm_kernel, cudaFuncAttributeMaxDynamicSharedMemorySize, SMEM_DYN);

    dim3 grid(2 * KSPLIT, MTILES);              // (16, 64) = 1024 CTAs
    gemm_kernel<<<grid, NTHREADS, SMEM_DYN>>>(hs, W);

    // route kernel as a PDL secondary: may start while the GEMM drains
    cudaLaunchConfig_t cfg = {};
    cfg.gridDim  = dim3(MTILES, 1, 1);
    cfg.blockDim = dim3(256, 1, 1);
    cfg.dynamicSmemBytes = 0;
    cudaLaunchAttribute attrs[1];
    attrs[0].id = cudaLaunchAttributeProgrammaticStreamSerialization;
    attrs[0].val.programmaticStreamSerializationAllowed = 1;
    cfg.attrs = attrs;
    cfg.numAttrs = 1;
    cudaLaunchKernelEx(&cfg, route_kernel, bias, out);
}

// round 14
// speedup vs baseline: 1.2667x; 1.2667x over previous
#include <cuda_runtime.h>
#include <cstdint>
#include <math.h>

#define TOKENS 8192
#define HIDDEN 7168
#define NEXP   256
#define TOP_K  8

// ---- GEMM: CTA 128x128xK896, 8 warps (2x4, warp 64x32), 2 CTAs/SM ----------
// [R9 kernel, byte-identical: zero register margin — DO NOT MODIFY]
#define BM 128
#define BN 128
#define BK 32
#define KSPLIT 8
#define KSLICE (HIDDEN / KSPLIT)    // 896
#define KT_ITERS (KSLICE / BK)      // 28
#define STAGES 3
#define NTHREADS 256
#define ASTRIDE 36                  // banks (4m+k) all distinct
#define BSTRIDE 136                 // banks (8k+n) all distinct
#define A_FLOATS (BM * ASTRIDE)     // 4608
#define B_FLOATS (BK * BSTRIDE)     // 4352
#define STAGE_FLOATS (A_FLOATS + B_FLOATS)      // 8960
#define SMEM_DYN (STAGES * STAGE_FLOATS * 4)    // 107520 B -> 2 CTAs/SM

// device scratch (no cudaMalloc allowed)
__device__ float g_part[KSPLIT][(size_t)TOKENS * NEXP];

__device__ __forceinline__ uint32_t smem_u32(const void* p) {
    uint32_t a;
    asm("{ .reg .u64 t; cvta.to.shared.u64 t, %1; cvt.u32.u64 %0, t; }" : "=r"(a) : "l"(p));
    return a;
}
__device__ __forceinline__ void cp_async16(uint32_t s, const void* g) {
    asm volatile("cp.async.cg.shared.global [%0], [%1], 16;\n" :: "r"(s), "l"(g));
}
__device__ __forceinline__ void mma_tf32(float* c, const uint32_t* a, const uint32_t* b) {
    asm volatile(
        "mma.sync.aligned.m16n8k8.row.col.f32.tf32.tf32.f32 "
        "{%0,%1,%2,%3}, {%4,%5,%6,%7}, {%8,%9}, {%0,%1,%2,%3};\n"
        : "+f"(c[0]), "+f"(c[1]), "+f"(c[2]), "+f"(c[3])
        : "r"(a[0]), "r"(a[1]), "r"(a[2]), "r"(a[3]), "r"(b[0]), "r"(b[1]));
}

// ---------------------------------------------------------------------------
// GEMM: g_part[ksl] = A[mtile rows, kslice] * B[kslice, ntile cols]
// grid (16, 64): x = ntile + 2*ksl, y = mtile.  1024 CTAs, ~3.5 waves;
// the HW scheduler load-balances the tail.
// ---------------------------------------------------------------------------
__global__ __launch_bounds__(NTHREADS, 2) void gemm_kernel(
    const float* __restrict__ A, const float* __restrict__ B)
{
    extern __shared__ float smem[];

    const int tid    = threadIdx.x;
    const int wid    = tid >> 5;
    const int lane   = tid & 31;
    const int warp_m = wid >> 2;    // 0..1 -> 64 rows
    const int warp_n = wid & 3;     // 0..3 -> 32 cols
    const int ntile  = blockIdx.x & 1;
    const int ksl    = blockIdx.x >> 1;
    const int brow   = blockIdx.y * BM;
    const int bcol   = ntile * BN;
    const int kbase  = ksl * KSLICE;

    // per-thread load slots: A 1024 chunks (4/thr), B 1024 chunks (4/thr)
    const float* agp[4]; uint32_t aof[4];
    const float* bgp[4]; uint32_t bof[4];
    #pragma unroll
    for (int j = 0; j < 4; j++) {
        int i = tid + j * 256;          // A: 128 rows x 8 chunks of 16B
        int r = i >> 3, c = i & 7;
        aof[j] = (uint32_t)(r * ASTRIDE + c * 4) * 4u;
        agp[j] = A + (size_t)(brow + r) * HIDDEN + kbase + c * 4;
    }
    #pragma unroll
    for (int j = 0; j < 4; j++) {
        int i = tid + j * 256;          // B: 32 rows x 32 chunks of 16B
        int r = i >> 5, c = i & 31;
        bof[j] = (uint32_t)(A_FLOATS + r * BSTRIDE + c * 4) * 4u;
        bgp[j] = B + (size_t)(kbase + r) * NEXP + bcol + c * 4;
    }
    const uint32_t smem_base = smem_u32(smem);

    auto load_stage = [&](int kt) {
        const uint32_t sbase = smem_base + (uint32_t)(kt % STAGES) * (STAGE_FLOATS * 4);
        const int koff = kt * BK;
        #pragma unroll
        for (int j = 0; j < 4; j++) cp_async16(sbase + aof[j], agp[j] + koff);
        #pragma unroll
        for (int j = 0; j < 4; j++) cp_async16(sbase + bof[j], bgp[j] + (size_t)koff * NEXP);
        asm volatile("cp.async.commit_group;\n" ::: "memory");
    };

    float acc[4][4][4];
    #pragma unroll
    for (int mt = 0; mt < 4; mt++)
        #pragma unroll
        for (int nt = 0; nt < 4; nt++)
            #pragma unroll
            for (int i = 0; i < 4; i++) acc[mt][nt][i] = 0.f;

    load_stage(0);
    load_stage(1);

    const int arow0 = warp_m * 64 + (lane >> 2);
    const int bcol0 = warp_n * 32 + (lane >> 2);
    const int ak    = lane & 3;

    for (int kt = 0; kt < KT_ITERS; kt++) {
        if (kt == KT_ITERS - 1)
            asm volatile("cp.async.wait_group 0;\n" ::: "memory");
        else
            asm volatile("cp.async.wait_group 1;\n" ::: "memory");
        __syncthreads();      // single barrier per kt (also guards buffer reuse)

        if (kt + 2 < KT_ITERS) load_stage(kt + 2);

        const float* As = smem + (size_t)(kt % STAGES) * STAGE_FLOATS;
        const float* Bs = As + A_FLOATS;

        #pragma unroll
        for (int ks = 0; ks < 4; ks++) {
            const int kk = ks * 8;
            uint32_t afr[4][4];
            uint32_t bfr[4][2];
            #pragma unroll
            for (int mt = 0; mt < 4; mt++) {
                const int m0 = arow0 + mt * 16;
                const int cc = kk + ak;
                afr[mt][0] = __float_as_uint(As[m0 * ASTRIDE + cc]);
                afr[mt][1] = __float_as_uint(As[(m0 + 8) * ASTRIDE + cc]);
                afr[mt][2] = __float_as_uint(As[m0 * ASTRIDE + cc + 4]);
                afr[mt][3] = __float_as_uint(As[(m0 + 8) * ASTRIDE + cc + 4]);
            }
            #pragma unroll
            for (int nt = 0; nt < 4; nt++) {
                const int n0 = bcol0 + nt * 8;
                const int kr = kk + ak;
                bfr[nt][0] = __float_as_uint(Bs[kr * BSTRIDE + n0]);
                bfr[nt][1] = __float_as_uint(Bs[(kr + 4) * BSTRIDE + n0]);
            }
            #pragma unroll
            for (int mt = 0; mt < 4; mt++)
                #pragma unroll
                for (int nt = 0; nt < 4; nt++)
                    mma_tf32(acc[mt][nt], afr[mt], bfr[nt]);
        }
    }

    // epilogue: plain stores into this k-slice's partial buffer
    float* dst = g_part[ksl];
    #pragma unroll
    for (int mt = 0; mt < 4; mt++) {
        #pragma unroll
        for (int nt = 0; nt < 4; nt++) {
            int row = brow + warp_m * 64 + mt * 16 + (lane >> 2);
            int col = bcol + warp_n * 32 + nt * 8 + (lane & 3) * 2;
            *(float2*)&dst[(size_t)row * NEXP + col] =
                make_float2(acc[mt][nt][0], acc[mt][nt][1]);
            *(float2*)&dst[(size_t)(row + 8) * NEXP + col] =
                make_float2(acc[mt][nt][2], acc[mt][nt][3]);
        }
    }
}

// ---------------------------------------------------------------------------
// Routing: sum 8 partials (fixed order), MUFU sigmoid + bias, group top-2
// sums, top-4 groups, top-8 experts, renormalize * 2.5. One warp per token.
// [R9 structure: 1024 blocks x 8 warps; __expf + hoisted bias only deltas]
// ---------------------------------------------------------------------------
__global__ __launch_bounds__(256) void route_kernel(
    const float* __restrict__ bias, float* __restrict__ out)
{
    const int lane  = threadIdx.x & 31;
    const int token = blockIdx.x * 8 + (threadIdx.x >> 5);
    if (token >= TOKENS) return;

    float bias_r[8];
    #pragma unroll
    for (int i = 0; i < 8; i++) bias_r[i] = __ldg(&bias[lane * 8 + i]);

    // sum the 8 k-slice partials in fixed order (deterministic)
    float l[8] = {0.f, 0.f, 0.f, 0.f, 0.f, 0.f, 0.f, 0.f};
    #pragma unroll
    for (int b = 0; b < KSPLIT; b++) {
        const float4* p = (const float4*)(g_part[b] + (size_t)token * NEXP + lane * 8);
        float4 x = p[0], y = p[1];
        l[0] += x.x; l[1] += x.y; l[2] += x.z; l[3] += x.w;
        l[4] += y.x; l[5] += y.y; l[6] += y.z; l[7] += y.w;
    }

    float s[8];
    #pragma unroll
    for (int i = 0; i < 8; i++) {
        float sc = 1.f / (1.f + __expf(-l[i]));
        s[i] = sc + bias_r[i];
    }

    float m1 = -INFINITY, m2 = -INFINITY;
    #pragma unroll
    for (int i = 0; i < 8; i++) {
        float v = s[i];
        if (v > m1) { m2 = m1; m1 = v; }
        else if (v > m2) { m2 = v; }
    }
    #pragma unroll
    for (int off = 1; off <= 2; off <<= 1) {
        float o1 = __shfl_xor_sync(0xffffffffu, m1, off);
        float o2 = __shfl_xor_sync(0xffffffffu, m2, off);
        float hi = fmaxf(m1, o1);
        float lo = fmaxf(fminf(m1, o1), fmaxf(m2, o2));
        m1 = hi; m2 = lo;
    }
    float gsum = m1 + m2;

    float gs[8];
    #pragma unroll
    for (int g = 0; g < 8; g++)
        gs[g] = __shfl_sync(0xffffffffu, gsum, g * 4);

    const int myg = lane >> 2;
    int rank = 0;
    #pragma unroll
    for (int h = 0; h < 8; h++)
        if (gs[h] > gs[myg] || (gs[h] == gs[myg] && h < myg)) rank++;
    const bool sel = rank < 4;

    float vals[8];
    #pragma unroll
    for (int i = 0; i < 8; i++) vals[i] = sel ? s[i] : 0.f;

    float w[TOP_K];
    #pragma unroll
    for (int t = 0; t < TOP_K; t++) {
        float bv = vals[0];
        int bi = 0;
        #pragma unroll
        for (int i = 1; i < 8; i++)
            if (vals[i] > bv) { bv = vals[i]; bi = i; }
        int bidx = lane * 8 + bi;
        #pragma unroll
        for (int off = 16; off >= 1; off >>= 1) {
            float ov = __shfl_xor_sync(0xffffffffu, bv, off);
            int   oi = __shfl_xor_sync(0xffffffffu, bidx, off);
            if (ov > bv || (ov == bv && oi < bidx)) { bv = ov; bidx = oi; }
        }
        w[t] = bv;
        if ((bidx >> 3) == lane) vals[bidx & 7] = -INFINITY;
    }

    float denom = 1e-20f;
    #pragma unroll
    for (int t = 0; t < TOP_K; t++) denom += w[t];
    const float scale = 2.5f / denom;

    if (lane == 0) {
        #pragma unroll
        for (int t = 0; t < TOP_K; t++)
            out[(size_t)token * TOP_K + t] = w[t] * scale;
    }
}

// ---------------------------------------------------------------------------
extern "C" void kernel_launch(void* const* d_in, const int* in_sizes, int n_in,
                              void* d_out, int out_size)
{
    (void)in_sizes; (void)n_in; (void)out_size;
    const float* hs   = (const float*)d_in[0];  // [8192, 7168]
    const float* W    = (const float*)d_in[1];  // [7168, 256]
    const float* bias = (const float*)d_in[2];  // [256]
    float* out = (float*)d_out;                 // [8192, 8]

    cudaFuncSetAttribute(gemm_kernel, cudaFuncAttributeMaxDynamicSharedMemorySize, SMEM_DYN);

    dim3 grid(2 * KSPLIT, TOKENS / BM);         // (16, 64) = 1024 CTAs
    gemm_kernel<<<grid, NTHREADS, SMEM_DYN>>>(hs, W);
    route_kernel<<<TOKENS / 8, 256>>>(bias, out);
}